// round 7
// baseline (speedup 1.0000x reference)
#include <cuda_runtime.h>
#include <cuda_fp16.h>
#include <cstdint>

// ===========================================================================
// One CTA per m. GEMM rows grouped by l: tile mt=l covers rows q=0..15
// (q=1..14 valid <-> n=q-1; q=0,15 garbage). A row in xs: u = l*16 + q + tap.
// xs[u][j]: u = l*16 + h + 2 holds x[j][l*14+h]; rows u%16 in {0,1} are the
// shared zero pads (h=-1 / h=14 of adjacent tiles).
// Epilogue: warp (l,ng) writes out rows p=(l+1)%14 from own accum (w1[:,0])
// + neighbor tile (l-1)%14 read from t4s (w1[:,1]).
// ===========================================================================

__device__ __half g_Bh[256 * 384];   // w2^T fp16: [c][kk], kk = k*128+j

__device__ __forceinline__ uint32_t smem_u32(const void* p) {
    uint32_t a;
    asm("{ .reg .u64 t; cvta.to.shared.u64 t, %1; cvt.u32.u64 %0, t; }" : "=r"(a) : "l"(p));
    return a;
}

__global__ __launch_bounds__(256) void kB(const float* __restrict__ w2) {
    int i = blockIdx.x * 256 + threadIdx.x;          // 98304 total
    if (i >= 98304) return;
    int c  = i / 384;
    int kk = i - c * 384;
    int k  = kk >> 7;
    int j  = kk & 127;
    g_Bh[i] = __float2half(w2[j * 768 + k * 256 + c]);
}

static constexpr int XS_STRIDE = 136;   // halves (272B rows; ldmatrix conflict-free)
static constexpr int BS_STRIDE = 392;   // halves
static constexpr int T4_STRIDE = 136;   // halves (68 words: 4*q0+t bank pattern)

static constexpr int XS_OFF = 0;                      // 226*136*2 = 61472 B
static constexpr int BS_OFF = 61472;                  // 128*392*2 = 100352 B
static constexpr int T4_OFF = 161824;                 // 224*136*2 = 60928 B
static constexpr int SMEM_BYTES = 222752;

struct GemmCtx {
    uint32_t a_pre, b_pre;
    bool active;
};

__device__ __forceinline__ void gemm_phase(float (&d)[8][4], const GemmCtx& g) {
    #pragma unroll
    for (int i = 0; i < 8; i++)
        #pragma unroll
        for (int q = 0; q < 4; q++) d[i][q] = 0.f;
    if (!g.active) return;
    #pragma unroll 4
    for (int s = 0; s < 24; s++) {
        const int tap = s >> 3;
        uint32_t a_addr = g.a_pre + (uint32_t)(tap * (XS_STRIDE * 2) + (s & 7) * 32);
        uint32_t a0, a1, a2, a3;
        asm volatile("ldmatrix.sync.aligned.m8n8.x4.shared.b16 {%0,%1,%2,%3}, [%4];"
                     : "=r"(a0), "=r"(a1), "=r"(a2), "=r"(a3) : "r"(a_addr));
        uint32_t b_addr = g.b_pre + (uint32_t)(s * 32);
        #pragma unroll
        for (int q = 0; q < 4; q++) {
            uint32_t b0, b1, b2, b3;
            asm volatile("ldmatrix.sync.aligned.m8n8.x4.shared.b16 {%0,%1,%2,%3}, [%4];"
                         : "=r"(b0), "=r"(b1), "=r"(b2), "=r"(b3) : "r"(b_addr));
            b_addr += 16u * BS_STRIDE * 2u;
            asm volatile("mma.sync.aligned.m16n8k16.row.col.f32.f16.f16.f32 "
                         "{%0,%1,%2,%3}, {%4,%5,%6,%7}, {%8,%9}, {%0,%1,%2,%3};"
                         : "+f"(d[2*q][0]), "+f"(d[2*q][1]),
                           "+f"(d[2*q][2]), "+f"(d[2*q][3])
                         : "r"(a0), "r"(a1), "r"(a2), "r"(a3), "r"(b0), "r"(b1));
            asm volatile("mma.sync.aligned.m16n8k16.row.col.f32.f16.f16.f32 "
                         "{%0,%1,%2,%3}, {%4,%5,%6,%7}, {%8,%9}, {%0,%1,%2,%3};"
                         : "+f"(d[2*q+1][0]), "+f"(d[2*q+1][1]),
                           "+f"(d[2*q+1][2]), "+f"(d[2*q+1][3])
                         : "r"(a0), "r"(a1), "r"(a2), "r"(a3), "r"(b2), "r"(b3));
        }
    }
}

__global__ __launch_bounds__(1024, 1) void kMain(const float* __restrict__ x,
                                                 const float* __restrict__ w1,
                                                 float* __restrict__ out) {
    extern __shared__ char smem[];
    __half* xs  = (__half*)(smem + XS_OFF);
    __half* Bs  = (__half*)(smem + BS_OFF);
    __half* t4s = (__half*)(smem + T4_OFF);

    const int tid  = threadIdx.x;
    const int m    = blockIdx.x;
    const int wid  = tid >> 5;
    const int lane = tid & 31;

    // ================= Phase A: zero pads + build xs + load Bs(0) ==========
    {   // zero rows u%16 in {0,1} (28 rows) plus garbage rows 224,225
        uint32_t* xz = (uint32_t*)xs;
        for (int i = tid; i < 30 * 64; i += 1024) {
            int r   = i >> 6;
            int row = (r < 28) ? ((r >> 1) * 16 + (r & 1)) : (224 + (r - 28));
            xz[(row * XS_STRIDE) / 2 + (i & 63)] = 0;
        }
    }
    const float* xm = x + (size_t)m * 25088;
    for (int i = tid; i < 25088; i += 1024) {      // coalesced LDG, strided STS.U16
        int j  = i / 196;
        int lh = i - j * 196;
        int l  = lh / 14;
        int h  = lh - l * 14;
        xs[(l * 16 + h + 2) * XS_STRIDE + j] = __float2half(xm[i]);
    }
    {
        const uint32_t* src = (const uint32_t*)g_Bh;          // hc=0
        for (int i = tid; i < 128 * 192; i += 1024) {
            int c  = i / 192;
            int kw = i - c * 192;
            *(uint32_t*)(Bs + c * BS_STRIDE + kw * 2) = src[i];
        }
    }

    // ---- per-warp constants ----
    const bool active = wid < 28;
    const int  mt     = active ? (wid % 14) : 0;
    const int  ngrp   = active ? (wid / 14) : 0;
    const int  cbase  = ngrp * 8;

    GemmCtx g;
    g.active = active;
    g.a_pre  = smem_u32(xs) +
        (uint32_t)(((mt * 16 + (lane & 15)) * XS_STRIDE + ((lane >> 4) << 3)) * 2);
    {
        const int n_in16 = (((lane >> 4) & 1) << 3) + (lane & 7);
        const int k_half = ((lane >> 3) & 1) << 3;
        g.b_pre = smem_u32(Bs) +
            (uint32_t)(((cbase * 8 + n_in16) * BS_STRIDE + k_half) * 2);
    }

    const int q0 = lane >> 2;           // 0..7
    const int tq = lane & 3;
    const int l2 = (mt + 13) % 14;      // neighbor tile
    const int p  = (mt + 1) % 14;       // output spatial row produced
    float* om = out + (size_t)m * 50176;

    float d[8][4];
    __syncthreads();

    // ================= hc = 0 ==============================================
    gemm_phase(d, g);                                   // Phase B
    __syncthreads();

    // Phase C: t4s stores + Bs(1) load
    if (active) {
        #pragma unroll
        for (int i = 0; i < 8; i++) {
            const int c0 = (cbase + i) * 8 + tq * 2;
            *(__half2*)(t4s + (mt * 16 + q0) * T4_STRIDE + c0) =
                __floats2half2_rn(d[i][0], d[i][1]);
            *(__half2*)(t4s + (mt * 16 + q0 + 8) * T4_STRIDE + c0) =
                __floats2half2_rn(d[i][2], d[i][3]);
        }
    }
    {
        const uint32_t* src = (const uint32_t*)(g_Bh + 128 * 384);   // hc=1
        for (int i = tid; i < 128 * 192; i += 1024) {
            int c  = i / 192;
            int kw = i - c * 192;
            *(uint32_t*)(Bs + c * BS_STRIDE + kw * 2) = src[i];
        }
    }
    __syncthreads();

    // Phase D: epilogue(0) then GEMM(1), no barrier between
    if (active) {
        #pragma unroll
        for (int i = 0; i < 8; i++) {
            const int c0 = (cbase + i) * 8 + tq * 2;
            const int cg = c0;                                   // hc=0
            float4 w4 = *(const float4*)(w1 + 2 * cg);
            float2 f01 = __half22float2(
                *(const __half2*)(t4s + (l2 * 16 + q0) * T4_STRIDE + c0));
            float2 f23 = __half22float2(
                *(const __half2*)(t4s + (l2 * 16 + q0 + 8) * T4_STRIDE + c0));
            const int base = cg * 196 + p * 14;
            if (q0 >= 1) {
                om[base + q0 - 1]       = w4.x * d[i][0] + w4.y * f01.x;
                om[base + 196 + q0 - 1] = w4.z * d[i][1] + w4.w * f01.y;
            }
            if (q0 <= 6) {
                om[base + q0 + 7]       = w4.x * d[i][2] + w4.y * f23.x;
                om[base + 196 + q0 + 7] = w4.z * d[i][3] + w4.w * f23.y;
            }
        }
    }
    gemm_phase(d, g);                                   // hc=1 GEMM
    __syncthreads();

    // Phase E: t4s stores(1)
    if (active) {
        #pragma unroll
        for (int i = 0; i < 8; i++) {
            const int c0 = (cbase + i) * 8 + tq * 2;
            *(__half2*)(t4s + (mt * 16 + q0) * T4_STRIDE + c0) =
                __floats2half2_rn(d[i][0], d[i][1]);
            *(__half2*)(t4s + (mt * 16 + q0 + 8) * T4_STRIDE + c0) =
                __floats2half2_rn(d[i][2], d[i][3]);
        }
    }
    __syncthreads();

    // Phase F: epilogue(1)
    if (active) {
        #pragma unroll
        for (int i = 0; i < 8; i++) {
            const int c0 = (cbase + i) * 8 + tq * 2;
            const int cg = 128 + c0;                             // hc=1
            float4 w4 = *(const float4*)(w1 + 2 * cg);
            float2 f01 = __half22float2(
                *(const __half2*)(t4s + (l2 * 16 + q0) * T4_STRIDE + c0));
            float2 f23 = __half22float2(
                *(const __half2*)(t4s + (l2 * 16 + q0 + 8) * T4_STRIDE + c0));
            const int base = cg * 196 + p * 14;
            if (q0 >= 1) {
                om[base + q0 - 1]       = w4.x * d[i][0] + w4.y * f01.x;
                om[base + 196 + q0 - 1] = w4.z * d[i][1] + w4.w * f01.y;
            }
            if (q0 <= 6) {
                om[base + q0 + 7]       = w4.x * d[i][2] + w4.y * f23.x;
                om[base + 196 + q0 + 7] = w4.z * d[i][3] + w4.w * f23.y;
            }
        }
    }
}

// ===========================================================================
extern "C" void kernel_launch(void* const* d_in, const int* in_sizes, int n_in,
                              void* d_out, int out_size) {
    const float* x  = (const float*)d_in[0];   // (1024, 1792, 14)
    const float* w1 = (const float*)d_in[1];   // (256, 2)
    const float* w2 = (const float*)d_in[2];   // (128, 3, 256)
    float* out = (float*)d_out;                // (1024, 256, 14, 14)

    static int attr_done = 0;
    if (!attr_done) {
        cudaFuncSetAttribute(kMain, cudaFuncAttributeMaxDynamicSharedMemorySize,
                             SMEM_BYTES);
        attr_done = 1;
    }

    kB<<<384, 256>>>(w2);
    kMain<<<1024, 1024, SMEM_BYTES>>>(x, w1, out);
}